// round 12
// baseline (speedup 1.0000x reference)
#include <cuda_runtime.h>
#include <cstdint>

// Embedding gather: out[r, :] = weight[ids[r], :]
// weight: [50257, 1024] fp32, ids: [32768] int32, out: [32768, 1024] fp32
//
// R12: consolidation. Best-known config:
//   - 8 rows/CTA, 256 threads, one float4 column slot per thread
//   - gathers: ld.global.cg (L2-only; random rows never hit L1, so skip the
//     L1 fill/replay overhead on the latency-critical path)
//   - stores: st.global.wt (write-through; R11 showed this is the fastest
//     write path — no L2 allocation churn for the write-once 128MB stream)
// L2 residency hints (evict_last policy) were proven no-ops in R9-R11 and
// are removed.

#define DIM4 256          // DIM/4 float4 per row
#define THREADS 256
#define ROWS_PER_CTA 8

__global__ __launch_bounds__(THREADS)
void embed_gather_kernel(const float4* __restrict__ weight,
                         const int* __restrict__ ids,
                         float4* __restrict__ out,
                         int n_rows)
{
    const int tid  = threadIdx.x;
    const int base = blockIdx.x * ROWS_PER_CTA;

    // 8 independent broadcast index loads (L2-hot, one wait)
    int idx[ROWS_PER_CTA];
#pragma unroll
    for (int r = 0; r < ROWS_PER_CTA; r++)
        idx[r] = ids[base + r];

    // 8 independent 16B gathers, L2-only path
    float v[ROWS_PER_CTA][4];
#pragma unroll
    for (int r = 0; r < ROWS_PER_CTA; r++) {
        const float4* src = weight + (size_t)idx[r] * DIM4 + tid;
        asm("ld.global.cg.v4.f32 {%0, %1, %2, %3}, [%4];"
            : "=f"(v[r][0]), "=f"(v[r][1]), "=f"(v[r][2]), "=f"(v[r][3])
            : "l"(src));
    }

    // 8 write-through stores (no L2 allocation for write-once output)
#pragma unroll
    for (int r = 0; r < ROWS_PER_CTA; r++) {
        float4* dst = out + (size_t)(base + r) * DIM4 + tid;
        asm volatile("st.global.wt.v4.f32 [%0], {%1, %2, %3, %4};"
                     :: "l"(dst),
                        "f"(v[r][0]), "f"(v[r][1]), "f"(v[r][2]), "f"(v[r][3])
                     : "memory");
    }
}

extern "C" void kernel_launch(void* const* d_in, const int* in_sizes, int n_in,
                              void* d_out, int out_size)
{
    // Identify inputs by element count:
    //   weight: 50257*1024 = 51463168 elements; ids: 32768 elements
    const float4* weight;
    const int* ids;
    int n_rows;

    if (in_sizes[0] > in_sizes[1]) {
        weight = (const float4*)d_in[0];
        ids    = (const int*)d_in[1];
        n_rows = in_sizes[1];
    } else {
        weight = (const float4*)d_in[1];
        ids    = (const int*)d_in[0];
        n_rows = in_sizes[0];
    }

    int n_blocks = n_rows / ROWS_PER_CTA;  // 32768/8 = 4096, exact
    embed_gather_kernel<<<n_blocks, THREADS>>>(weight, ids, (float4*)d_out, n_rows);
}